// round 15
// baseline (speedup 1.0000x reference)
#include <cuda_runtime.h>
#include <cuda_fp16.h>
#include <stdint.h>

#define BATCH   4096
#define IN_DIM  16384
#define OUT_DIM 16384
#define THREADS 1024
#define NCONS   768               // consumer threads (warps 0-23)
#define NPROD   256               // producer threads (warps 24-31)
#define PAIRS   (BATCH / 2)       // 2048
#define CHUNK_COLS 4096           // columns per TMA chunk
#define CHUNK_BYTES (CHUNK_COLS * 4 * 2)   // 32KB: both rows' segment
#define NCHUNK  (IN_DIM / CHUNK_COLS)      // 4 chunks per pair
#define SLOT_BYTES (IN_DIM * 4)            // 64KB half2-interleaved

// Per-j k coefficients, 8B: x = half2(k0,k1), y = half2(k2,k3)
__device__ uint2    g_k8[OUT_DIM];
// Per-j packed indices: a | (b<<16)
__device__ uint32_t g_idx_pack[OUT_DIM];
// Dynamic work queue counter
__device__ int g_ctr;

__constant__ float c_gate[16][4] = {
    {0.f, 0.f, 0.f, 0.f}, {0.f, 0.f, 0.f, 1.f}, {0.f, 1.f, 0.f,-1.f}, {0.f, 1.f, 0.f, 0.f},
    {0.f, 0.f, 1.f,-1.f}, {0.f, 0.f, 1.f, 0.f}, {0.f, 1.f, 1.f,-2.f}, {0.f, 1.f, 1.f,-1.f},
    {1.f,-1.f,-1.f, 1.f}, {1.f,-1.f,-1.f, 2.f}, {1.f, 0.f,-1.f, 0.f}, {1.f, 0.f,-1.f, 1.f},
    {1.f,-1.f, 0.f, 0.f}, {1.f,-1.f, 0.f, 1.f}, {1.f, 0.f, 0.f,-1.f}, {1.f, 0.f, 0.f, 0.f}
};

// int64-vs-int32 buffer detection (R1 fix).
__device__ __forceinline__ bool idx_is_int64(const int* p) {
    bool odd_all_zero = true;
    #pragma unroll
    for (int i = 1; i < 64; i += 2) odd_all_zero &= (p[i] == 0);
    return odd_all_zero;
}
__device__ __forceinline__ int load_index(const void* base, int j, bool is64) {
    if (is64) return (int)((const long long*)base)[j];
    return ((const int*)base)[j];
}

__global__ void prep_kernel(const float* __restrict__ w,
                            const void* __restrict__ a_idx,
                            const void* __restrict__ b_idx,
                            int ncta)
{
    int j = blockIdx.x * blockDim.x + threadIdx.x;
    if (j == 0) g_ctr = ncta;   // first ncta pairs statically assigned
    if (j >= OUT_DIM) return;

    const bool a64 = idx_is_int64((const int*)a_idx);
    const bool b64 = idx_is_int64((const int*)b_idx);

    float wv[16];
    const float4* w4 = reinterpret_cast<const float4*>(w + (size_t)j * 16);
    #pragma unroll
    for (int q = 0; q < 4; q++) {
        float4 v = __ldg(&w4[q]);
        wv[q*4+0] = v.x; wv[q*4+1] = v.y; wv[q*4+2] = v.z; wv[q*4+3] = v.w;
    }
    float m = wv[0];
    #pragma unroll
    for (int i = 1; i < 16; i++) m = fmaxf(m, wv[i]);
    float e[16], s = 0.f;
    #pragma unroll
    for (int i = 0; i < 16; i++) { e[i] = __expf(wv[i] - m); s += e[i]; }
    float inv = 1.0f / s;

    float k0 = 0.f, k1 = 0.f, k2 = 0.f, k3 = 0.f;
    #pragma unroll
    for (int i = 0; i < 16; i++) {
        float p = e[i] * inv;
        k0 = fmaf(p, c_gate[i][0], k0);
        k1 = fmaf(p, c_gate[i][1], k1);
        k2 = fmaf(p, c_gate[i][2], k2);
        k3 = fmaf(p, c_gate[i][3], k3);
    }

    unsigned int ia = (unsigned int)load_index(a_idx, j, a64);
    unsigned int ib = (unsigned int)load_index(b_idx, j, b64);

    __half2 h01 = __floats2half2_rn(k0, k1);
    __half2 h23 = __floats2half2_rn(k2, k3);
    uint2 k8;
    k8.x = *reinterpret_cast<unsigned int*>(&h01);
    k8.y = *reinterpret_cast<unsigned int*>(&h23);
    g_k8[j] = k8;
    g_idx_pack[j] = ia | (ib << 16);
}

// ---- mbarrier / TMA-bulk helpers ----
__device__ __forceinline__ uint32_t smem_u32(const void* p) {
    uint32_t a;
    asm("{ .reg .u64 t; cvta.to.shared.u64 t, %1; cvt.u32.u64 %0, t; }" : "=r"(a) : "l"(p));
    return a;
}
__device__ __forceinline__ void mbar_init(uint32_t mbar, uint32_t cnt) {
    asm volatile("mbarrier.init.shared.b64 [%0], %1;" :: "r"(mbar), "r"(cnt) : "memory");
}
__device__ __forceinline__ void mbar_expect_tx(uint32_t mbar, uint32_t bytes) {
    asm volatile("mbarrier.arrive.expect_tx.shared.b64 _, [%0], %1;"
                 :: "r"(mbar), "r"(bytes) : "memory");
}
__device__ __forceinline__ void mbar_wait(uint32_t mbar, uint32_t phase) {
    asm volatile(
        "{\n\t.reg .pred P;\n\t"
        "WL_%=:\n\t"
        "mbarrier.try_wait.parity.acquire.cta.shared::cta.b64 P, [%0], %1, 0x989680;\n\t"
        "@P bra.uni WD_%=;\n\t"
        "bra.uni WL_%=;\n\t"
        "WD_%=:\n\t}"
        :: "r"(mbar), "r"(phase) : "memory");
}
__device__ __forceinline__ void bulk_g2s(uint32_t dst, const void* src, uint32_t bytes, uint32_t mbar) {
    asm volatile(
        "cp.async.bulk.shared::cta.global.mbarrier::complete_tx::bytes [%0], [%1], %2, [%3];"
        :: "r"(dst), "l"(src), "r"(bytes), "r"(mbar) : "memory");
}
__device__ __forceinline__ void fence_proxy_async() {
    asm volatile("fence.proxy.async.shared::cta;" ::: "memory");
}

// Issue TMA for chunk c of pair p into ring slot (addr ringa, barrier mbar).
__device__ __forceinline__ void issue_chunk(const float* x, int p, int c,
                                            uint32_t ringa, uint32_t mbar)
{
    const float* src = x + (size_t)(2 * p) * IN_DIM + c * CHUNK_COLS;
    mbar_expect_tx(mbar, CHUNK_BYTES);
    bulk_g2s(ringa,                   src,          CHUNK_COLS * 4, mbar); // row even seg
    bulk_g2s(ringa + CHUNK_COLS * 4,  src + IN_DIM, CHUNK_COLS * 4, mbar); // row odd seg
}

// Evaluate one j for both rows of the pair.
__device__ __forceinline__ void eval2(uint32_t idxp, uint32_t k01u, uint32_t k23u,
                                      const __half2* __restrict__ xs,
                                      float& ve, float& vo)
{
    float2 k01 = __half22float2(*reinterpret_cast<__half2*>(&k01u));
    float2 k23 = __half22float2(*reinterpret_cast<__half2*>(&k23u));
    float2 a = __half22float2(xs[idxp & 0xFFFFu]);
    float2 b = __half22float2(xs[idxp >> 16]);
    ve = fmaf(a.x, fmaf(k23.y, b.x, k01.y), fmaf(k23.x, b.x, k01.x));
    vo = fmaf(a.y, fmaf(k23.y, b.y, k01.y), fmaf(k23.x, b.y, k01.x));
}

// Warp-specialized TMA pipeline, 1 CTA/SM, 1024 threads.
// smem: two 64KB half2-interleaved slots + 2x32KB raw chunk ring + mbarriers.
// Consumers (768 thr) compute pair `comp` from slot[s^1] while producers
// (256 thr) convert pair `fill`'s TMA chunks into slot[s] and re-issue the
// ring 2 chunks ahead (crossing into pair `fill2`): DRAM reads stream
// continuously, convert overlaps compute, one __syncthreads per pair.
__global__ void __launch_bounds__(THREADS, 1)
logic_main_kernel(const float* __restrict__ x, float* __restrict__ out)
{
    extern __shared__ __align__(16) unsigned char smem_raw[];
    __half2* slot[2] = {
        reinterpret_cast<__half2*>(smem_raw),
        reinterpret_cast<__half2*>(smem_raw + SLOT_BYTES)
    };
    const float4* ring4[2] = {
        reinterpret_cast<const float4*>(smem_raw + 2 * SLOT_BYTES),
        reinterpret_cast<const float4*>(smem_raw + 2 * SLOT_BYTES + CHUNK_BYTES)
    };
    uint32_t ring_a[2], mb[2];
    ring_a[0] = smem_u32(smem_raw + 2 * SLOT_BYTES);
    ring_a[1] = ring_a[0] + CHUNK_BYTES;
    mb[0] = smem_u32(smem_raw + 2 * SLOT_BYTES + 2 * CHUNK_BYTES);
    mb[1] = mb[0] + 8;
    __shared__ int s_pop[2];

    const int tid = threadIdx.x;

    if (tid == 0) {
        mbar_init(mb[0], 1);
        mbar_init(mb[1], 1);
        fence_proxy_async();
    }
    __syncthreads();

    int fill = blockIdx.x;       // pair streaming into slot[s]
    // Prologue: issue chunks 0,1 of `fill`; pop `fill2`.
    if (tid == 0) {
        issue_chunk(x, fill, 0, ring_a[0], mb[0]);
        issue_chunk(x, fill, 1, ring_a[1], mb[1]);
        s_pop[0] = atomicAdd(&g_ctr, 1);
    }
    __syncthreads();
    int fill2 = s_pop[0];
    int comp  = -1;              // pair in slot[s^1] (none yet)
    int s = 0, pi = 0;
    uint32_t n0 = 0, n1 = 0;     // producer ring-wait phase counters

    while ((comp >= 0 && comp < PAIRS) || fill < PAIRS) {
        const bool vfill = (fill < PAIRS);
        const bool vcomp = (comp >= 0 && comp < PAIRS);

        if (tid < NCONS) {
            // ---- consumers: compute `comp` from slot[s^1] ----
            if (vcomp) {
                const __half2* __restrict__ xs = slot[s ^ 1];
                float* __restrict__ oe = out + (size_t)(2 * comp) * OUT_DIM;
                float* __restrict__ oo = oe + OUT_DIM;
                #pragma unroll 4
                for (int j0 = 2 * tid; j0 < OUT_DIM; j0 += 2 * NCONS) {
                    uint2 I = __ldg(reinterpret_cast<const uint2*>(&g_idx_pack[j0]));
                    uint4 K = __ldg(reinterpret_cast<const uint4*>(&g_k8[j0]));
                    float2 ve, vo;
                    eval2(I.x, K.x, K.y, xs, ve.x, vo.x);
                    eval2(I.y, K.z, K.w, xs, ve.y, vo.y);
                    __stcs(reinterpret_cast<float2*>(&oe[j0]), ve);
                    __stcs(reinterpret_cast<float2*>(&oo[j0]), vo);
                }
            }
        } else if (vfill) {
            // ---- producers: convert `fill`'s 4 chunks into slot[s] ----
            const int pt = tid - NCONS;
            __half2* __restrict__ dst = slot[s];
            #pragma unroll
            for (int c = 0; c < NCHUNK; c++) {
                const int r = c & 1;
                uint32_t& n = r ? n1 : n0;
                mbar_wait(mb[r], n & 1);
                n++;

                const float4* __restrict__ rr = ring4[r];
                const int base = c * CHUNK_COLS;
                #pragma unroll
                for (int it = 0; it < CHUNK_COLS / (4 * NPROD); it++) {
                    int q = pt + it * NPROD;           // float4 index in chunk
                    float4 e = rr[q];                          // row even
                    float4 o = rr[(CHUNK_COLS / 4) + q];       // row odd
                    __half2 h0 = __floats2half2_rn(e.x, o.x);
                    __half2 h1 = __floats2half2_rn(e.y, o.y);
                    __half2 h2 = __floats2half2_rn(e.z, o.z);
                    __half2 h3 = __floats2half2_rn(e.w, o.w);
                    uint4 pk;
                    pk.x = *reinterpret_cast<unsigned int*>(&h0);
                    pk.y = *reinterpret_cast<unsigned int*>(&h1);
                    pk.z = *reinterpret_cast<unsigned int*>(&h2);
                    pk.w = *reinterpret_cast<unsigned int*>(&h3);
                    *reinterpret_cast<uint4*>(dst + base + 4 * q) = pk;
                }
                asm volatile("bar.sync 1, %0;" :: "n"(NPROD) : "memory");  // ring slot drained

                if (tid == NCONS) {
                    // re-issue this ring slot 2 chunks ahead
                    int ip, ic;
                    if (c < 2) { ip = fill;  ic = c + 2; }
                    else       { ip = fill2; ic = c - 2; }
                    if (ip < PAIRS) {
                        fence_proxy_async();
                        issue_chunk(x, ip, ic, ring_a[r], mb[r]);
                    }
                }
            }
        }

        if (tid == 0) s_pop[pi ^ 1] = atomicAdd(&g_ctr, 1);
        __syncthreads();   // slot[s] filled + slot[s^1] consumed + pop visible

        comp  = vfill ? fill : PAIRS;
        fill  = fill2;
        fill2 = s_pop[pi ^ 1];
        s ^= 1;
        pi ^= 1;
    }
}

extern "C" void kernel_launch(void* const* d_in, const int* in_sizes, int n_in,
                              void* d_out, int out_size)
{
    const float* x  = (const float*)d_in[0];
    const float* w  = (const float*)d_in[1];
    const void*  ai = d_in[2];
    const void*  bi = d_in[3];
    float* out = (float*)d_out;
    (void)in_sizes; (void)n_in; (void)out_size;

    int nsm = 148;
    cudaDeviceGetAttribute(&nsm, cudaDevAttrMultiProcessorCount, 0);
    const int ncta = nsm;   // 1 CTA per SM

    // 2x64KB slots + 2x32KB ring + mbarriers
    const int smem_bytes = 2 * SLOT_BYTES + 2 * CHUNK_BYTES + 64;
    cudaFuncSetAttribute(logic_main_kernel,
                         cudaFuncAttributeMaxDynamicSharedMemorySize, smem_bytes);

    prep_kernel<<<(OUT_DIM + 511) / 512, 512>>>(w, ai, bi, ncta);
    logic_main_kernel<<<ncta, THREADS, smem_bytes>>>(x, out);
}